// round 2
// baseline (speedup 1.0000x reference)
#include <cuda_runtime.h>

// Problem constants (fixed by the dataset)
#define DD 16
#define BB 8
#define EE 2048
#define OO 2048

#define ECH   16            // e's per chunk
#define NCHUNK (EE / ECH)   // 128
#define OTILE 1024          // o's per block (256 threads x float4)
#define NOT   (OO / OTILE)  // 2
#define NTHREADS 256

// Scratch: per-e-chunk partial output [chunk][b][o]  (128*8*2048*4B = 8 MB)
__device__ float g_partial[NCHUNK][BB][OO];

__global__ __launch_bounds__(NTHREADS)
void delta_synapse_main(const float* __restrict__ W,
                        const float* __restrict__ signs,
                        const float* __restrict__ Xd,
                        const float* __restrict__ Wshort,
                        const float* __restrict__ dmap) {
    // coef[g][el] with g = d*8+b : consecutive-tid writes hit consecutive banks
    __shared__ float    coef[DD * BB][ECH];
    __shared__ unsigned mask[ECH];          // bit d set if any b has coef!=0

    const int chunk = blockIdx.x;           // 0..127
    const int otile = blockIdx.y;           // 0..1
    const int e0    = chunk * ECH;
    const int obase = otile * OTILE + threadIdx.x * 4;

    if (threadIdx.x < ECH) mask[threadIdx.x] = 0u;
    __syncthreads();

    // ---- preload coefficients: coef[d*8+b][el] = Xd * (Wshort + 1) ----
    // total D*B*ECH = 2048 elements, 8 per thread
    for (int idx = threadIdx.x; idx < DD * BB * ECH; idx += NTHREADS) {
        const int el = idx & (ECH - 1);
        const int g  = idx / ECH;                 // d*8 + b
        const int gi = g * EE + e0 + el;          // (d*B+b)*E + e
        const float x = Xd[gi];
        const float c = x * (Wshort[gi] + 1.0f); // zero iff spike absent
        coef[g][el] = c;
        if (c != 0.0f) atomicOr(&mask[el], 1u << (g >> 3));
    }
    __syncthreads();

    float acc[BB][4];
    #pragma unroll
    for (int b = 0; b < BB; b++)
        #pragma unroll
        for (int j = 0; j < 4; j++) acc[b][j] = 0.0f;

    for (int el = 0; el < ECH; el++) {
        unsigned m = mask[el];                    // warp-uniform
        if (!m) continue;
        const int e = e0 + el;

        const float4 wv = *(const float4*)&W    [(size_t)e * OO + obase];
        const float4 sv = *(const float4*)&signs[(size_t)e * OO + obase];
        const float weff0 = wv.x * sv.x;
        const float weff1 = wv.y * sv.y;
        const float weff2 = wv.z * sv.z;
        const float weff3 = wv.w * sv.w;

        while (m) {                               // iterate active delays
            const int d = __ffs(m) - 1;
            m &= m - 1;
            const float4 dm =
                *(const float4*)&dmap[((size_t)d * EE + e) * OO + obase];
            const float t0 = weff0 * dm.x;
            const float t1 = weff1 * dm.y;
            const float t2 = weff2 * dm.z;
            const float t3 = weff3 * dm.w;
            #pragma unroll
            for (int b = 0; b < BB; b++) {
                const float c = coef[d * BB + b][el];  // smem broadcast, uniform
                if (c != 0.0f) {                       // warp-uniform branch
                    acc[b][0] += t0 * c;
                    acc[b][1] += t1 * c;
                    acc[b][2] += t2 * c;
                    acc[b][3] += t3 * c;
                }
            }
        }
    }

    // Write partials unconditionally (scratch is never zeroed)
    #pragma unroll
    for (int b = 0; b < BB; b++) {
        *(float4*)&g_partial[chunk][b][obase] =
            make_float4(acc[b][0], acc[b][1], acc[b][2], acc[b][3]);
    }
}

__global__ __launch_bounds__(256)
void delta_synapse_reduce(float* __restrict__ out) {
    const int idx = blockIdx.x * 256 + threadIdx.x;   // 0 .. B*O-1
    const float* p = &g_partial[0][0][0];
    float s0 = 0.f, s1 = 0.f, s2 = 0.f, s3 = 0.f;
    #pragma unroll 4
    for (int c = 0; c < NCHUNK; c += 4) {
        s0 += p[(size_t)(c + 0) * (BB * OO) + idx];
        s1 += p[(size_t)(c + 1) * (BB * OO) + idx];
        s2 += p[(size_t)(c + 2) * (BB * OO) + idx];
        s3 += p[(size_t)(c + 3) * (BB * OO) + idx];
    }
    out[idx] = (s0 + s1) + (s2 + s3);
}

extern "C" void kernel_launch(void* const* d_in, const int* in_sizes, int n_in,
                              void* d_out, int out_size) {
    (void)in_sizes; (void)n_in; (void)out_size;
    const float* W      = (const float*)d_in[0];
    const float* signs  = (const float*)d_in[1];
    const float* Xd     = (const float*)d_in[2];
    const float* Wshort = (const float*)d_in[3];
    const float* dmap   = (const float*)d_in[4];
    float* out = (float*)d_out;

    dim3 grid(NCHUNK, NOT);
    delta_synapse_main<<<grid, NTHREADS>>>(W, signs, Xd, Wshort, dmap);
    delta_synapse_reduce<<<(BB * OO) / 256, 256>>>(out);
}

// round 3
// speedup vs baseline: 1.0037x; 1.0037x over previous
#include <cuda_runtime.h>

// Problem constants (fixed by the dataset)
#define DD 16
#define BB 8
#define EE 2048
#define OO 2048

#define ECH   16            // e's per chunk
#define NCHUNK (EE / ECH)   // 128
#define OTILE 1024          // o's per block (256 threads x float4)
#define NOT   (OO / OTILE)  // 2
#define NTHREADS 256

// Scratch: per-e-chunk partial output [chunk][b][o]  (128*8*2048*4B = 8 MB)
__device__ float g_partial[NCHUNK][BB][OO];

__global__ __launch_bounds__(NTHREADS)
void delta_synapse_main(const float* __restrict__ W,
                        const float* __restrict__ signs,
                        const float* __restrict__ Xd,
                        const float* __restrict__ Wshort,
                        const float* __restrict__ dmap) {
    // coef[g][el] with g = d*8+b : consecutive-tid writes hit consecutive banks
    __shared__ float    coef[DD * BB][ECH];
    __shared__ unsigned mask[ECH];          // bit d set if any b has coef!=0

    const int chunk = blockIdx.x;           // 0..127
    const int otile = blockIdx.y;           // 0..1
    const int e0    = chunk * ECH;
    const int obase = otile * OTILE + threadIdx.x * 4;

    if (threadIdx.x < ECH) mask[threadIdx.x] = 0u;
    __syncthreads();

    // ---- preload coefficients: coef[d*8+b][el] = Xd * (Wshort + 1) ----
    // total D*B*ECH = 2048 elements, 8 per thread
    for (int idx = threadIdx.x; idx < DD * BB * ECH; idx += NTHREADS) {
        const int el = idx & (ECH - 1);
        const int g  = idx / ECH;                 // d*8 + b
        const int gi = g * EE + e0 + el;          // (d*B+b)*E + e
        const float x = Xd[gi];
        const float c = x * (Wshort[gi] + 1.0f); // zero iff spike absent
        coef[g][el] = c;
        if (c != 0.0f) atomicOr(&mask[el], 1u << (g >> 3));
    }
    __syncthreads();

    float acc[BB][4];
    #pragma unroll
    for (int b = 0; b < BB; b++)
        #pragma unroll
        for (int j = 0; j < 4; j++) acc[b][j] = 0.0f;

    for (int el = 0; el < ECH; el++) {
        unsigned m = mask[el];                    // warp-uniform
        if (!m) continue;
        const int e = e0 + el;

        const float4 wv = *(const float4*)&W    [(size_t)e * OO + obase];
        const float4 sv = *(const float4*)&signs[(size_t)e * OO + obase];
        const float weff0 = wv.x * sv.x;
        const float weff1 = wv.y * sv.y;
        const float weff2 = wv.z * sv.z;
        const float weff3 = wv.w * sv.w;

        while (m) {                               // iterate active delays
            const int d = __ffs(m) - 1;
            m &= m - 1;
            const float4 dm =
                *(const float4*)&dmap[((size_t)d * EE + e) * OO + obase];
            const float t0 = weff0 * dm.x;
            const float t1 = weff1 * dm.y;
            const float t2 = weff2 * dm.z;
            const float t3 = weff3 * dm.w;
            #pragma unroll
            for (int b = 0; b < BB; b++) {
                const float c = coef[d * BB + b][el];  // smem broadcast, uniform
                if (c != 0.0f) {                       // warp-uniform branch
                    acc[b][0] += t0 * c;
                    acc[b][1] += t1 * c;
                    acc[b][2] += t2 * c;
                    acc[b][3] += t3 * c;
                }
            }
        }
    }

    // Write partials unconditionally (scratch is never zeroed)
    #pragma unroll
    for (int b = 0; b < BB; b++) {
        *(float4*)&g_partial[chunk][b][obase] =
            make_float4(acc[b][0], acc[b][1], acc[b][2], acc[b][3]);
    }
}

__global__ __launch_bounds__(256)
void delta_synapse_reduce(float* __restrict__ out) {
    const int idx = blockIdx.x * 256 + threadIdx.x;   // 0 .. B*O-1
    const float* p = &g_partial[0][0][0];
    float s0 = 0.f, s1 = 0.f, s2 = 0.f, s3 = 0.f;
    #pragma unroll 4
    for (int c = 0; c < NCHUNK; c += 4) {
        s0 += p[(size_t)(c + 0) * (BB * OO) + idx];
        s1 += p[(size_t)(c + 1) * (BB * OO) + idx];
        s2 += p[(size_t)(c + 2) * (BB * OO) + idx];
        s3 += p[(size_t)(c + 3) * (BB * OO) + idx];
    }
    out[idx] = (s0 + s1) + (s2 + s3);
}

extern "C" void kernel_launch(void* const* d_in, const int* in_sizes, int n_in,
                              void* d_out, int out_size) {
    (void)in_sizes; (void)n_in; (void)out_size;
    const float* W      = (const float*)d_in[0];
    const float* signs  = (const float*)d_in[1];
    const float* Xd     = (const float*)d_in[2];
    const float* Wshort = (const float*)d_in[3];
    const float* dmap   = (const float*)d_in[4];
    float* out = (float*)d_out;

    dim3 grid(NCHUNK, NOT);
    delta_synapse_main<<<grid, NTHREADS>>>(W, signs, Xd, Wshort, dmap);
    delta_synapse_reduce<<<(BB * OO) / 256, 256>>>(out);
}

// round 4
// speedup vs baseline: 1.1128x; 1.1087x over previous
#include <cuda_runtime.h>

// Problem constants (fixed by the dataset)
#define DD 16
#define BB 8
#define EE 2048
#define OO 2048

#define ECH    16            // e's per chunk
#define NCHUNK (EE / ECH)    // 128
#define NTHREADS 128
#define OTILE  (NTHREADS * 4)   // 512 o's per block
#define NOT    (OO / OTILE)     // 4
#define PF     4             // prefetch pipeline depth

// Scratch: per-e-chunk partial output [chunk][b][o] (128*8*2048*4B = 8 MB)
__device__ float g_partial[NCHUNK][BB][OO];
// Stage-1 reduce intermediate: [8 chunk-groups][B*O] = 512 KB
__device__ float g_p2[8][BB * OO];

__global__ __launch_bounds__(NTHREADS)
void delta_synapse_main(const float* __restrict__ W,
                        const float* __restrict__ signs,
                        const float* __restrict__ Xd,
                        const float* __restrict__ Wshort,
                        const float* __restrict__ dmap) {
    __shared__ float    coef[DD * BB][ECH];     // 8 KB
    __shared__ float4   weffs[ECH][NTHREADS];   // 32 KB: W*signs per (el, thread)
    __shared__ unsigned mask[ECH];
    __shared__ unsigned short wl[ECH * DD];     // worklist: el | (d<<5)
    __shared__ int wl_n;

    const int chunk = blockIdx.x;               // 0..127
    const int otile = blockIdx.y;               // 0..3
    const int e0    = chunk * ECH;
    const int obase = otile * OTILE + threadIdx.x * 4;

    if (threadIdx.x < ECH) mask[threadIdx.x] = 0u;
    __syncthreads();

    // ---- Phase 1: coefficients coef[d*8+b][el] = Xd * (Wshort + 1) ----
    for (int idx = threadIdx.x; idx < DD * BB * ECH; idx += NTHREADS) {
        const int el = idx & (ECH - 1);
        const int g  = idx >> 4;                 // d*8 + b
        const int gi = g * EE + e0 + el;
        const float x = Xd[gi];
        const float c = x * (Wshort[gi] + 1.0f);
        coef[g][el] = c;
        if (c != 0.0f) atomicOr(&mask[el], 1u << (g >> 3));
    }
    __syncthreads();

    // ---- Phase 2: warp 0 builds compact worklist via prefix scan ----
    if (threadIdx.x < 32) {
        const int el = threadIdx.x;
        unsigned m = (el < ECH) ? mask[el] : 0u;
        const int cnt = __popc(m);
        int pre = cnt;                           // inclusive scan over 32 lanes
        #pragma unroll
        for (int off = 1; off < 32; off <<= 1) {
            int v = __shfl_up_sync(0xffffffffu, pre, off);
            if (threadIdx.x >= off) pre += v;
        }
        int pos = pre - cnt;
        while (m) {
            const int d = __ffs(m) - 1;
            m &= m - 1;
            wl[pos++] = (unsigned short)(el | (d << 5));
        }
        if (threadIdx.x == 31) wl_n = pre;
    }

    // ---- Phase 3: Weff = W*signs into smem (all 32 loads independent → MLP) ----
    #pragma unroll
    for (int el = 0; el < ECH; el++) {
        const size_t row = (size_t)(e0 + el) * OO + obase;
        const float4 wv = __ldcs((const float4*)&W[row]);
        const float4 sv = __ldcs((const float4*)&signs[row]);
        weffs[el][threadIdx.x] =
            make_float4(wv.x * sv.x, wv.y * sv.y, wv.z * sv.z, wv.w * sv.w);
    }
    __syncthreads();

    float acc[BB][4];
    #pragma unroll
    for (int b = 0; b < BB; b++)
        #pragma unroll
        for (int j = 0; j < 4; j++) acc[b][j] = 0.0f;

    // ---- Phase 4: pipelined sweep over worklist (delaymap is the only DRAM op) ----
    const int n = wl_n;
    float4 buf[PF];
    #pragma unroll
    for (int j = 0; j < PF; j++) {
        if (j < n) {
            const int w = wl[j];
            const size_t a = ((size_t)(w >> 5) * EE + e0 + (w & 31)) * OO + obase;
            buf[j] = __ldcs((const float4*)&dmap[a]);
        }
    }

    for (int i = 0; i < n; i += PF) {
        #pragma unroll
        for (int j = 0; j < PF; j++) {
            const int k = i + j;
            if (k >= n) break;
            const int w  = wl[k];
            const int el = w & 31;
            const int d  = w >> 5;
            const float4 dm = buf[j];

            const int p = k + PF;                 // prefetch next
            if (p < n) {
                const int w2 = wl[p];
                const size_t a = ((size_t)(w2 >> 5) * EE + e0 + (w2 & 31)) * OO + obase;
                buf[j] = __ldcs((const float4*)&dmap[a]);
            }

            const float4 wv = weffs[el][threadIdx.x];
            const float t0 = wv.x * dm.x;
            const float t1 = wv.y * dm.y;
            const float t2 = wv.z * dm.z;
            const float t3 = wv.w * dm.w;
            #pragma unroll
            for (int b = 0; b < BB; b++) {
                const float c = coef[d * BB + b][el];   // smem broadcast, warp-uniform
                if (c != 0.0f) {
                    acc[b][0] += t0 * c;
                    acc[b][1] += t1 * c;
                    acc[b][2] += t2 * c;
                    acc[b][3] += t3 * c;
                }
            }
        }
    }

    // ---- Phase 5: write partials (unconditional — scratch never zeroed) ----
    #pragma unroll
    for (int b = 0; b < BB; b++) {
        *(float4*)&g_partial[chunk][b][obase] =
            make_float4(acc[b][0], acc[b][1], acc[b][2], acc[b][3]);
    }
}

// Stage 1: 512 blocks — each sums 16 chunks for 256 (b,o) positions
__global__ __launch_bounds__(256)
void reduce_stage1() {
    const int idx = blockIdx.x * 256 + threadIdx.x;   // 0 .. B*O-1
    const int g   = blockIdx.y;                       // chunk group 0..7
    const float* p = &g_partial[0][0][0];
    float s0 = 0.f, s1 = 0.f, s2 = 0.f, s3 = 0.f;
    const int c0 = g * 16;
    #pragma unroll
    for (int c = 0; c < 16; c += 4) {
        s0 += p[(size_t)(c0 + c + 0) * (BB * OO) + idx];
        s1 += p[(size_t)(c0 + c + 1) * (BB * OO) + idx];
        s2 += p[(size_t)(c0 + c + 2) * (BB * OO) + idx];
        s3 += p[(size_t)(c0 + c + 3) * (BB * OO) + idx];
    }
    g_p2[g][idx] = (s0 + s1) + (s2 + s3);
}

// Stage 2: sum the 8 group-partials into the output
__global__ __launch_bounds__(256)
void reduce_stage2(float* __restrict__ out) {
    const int idx = blockIdx.x * 256 + threadIdx.x;
    float s = 0.f;
    #pragma unroll
    for (int g = 0; g < 8; g++) s += g_p2[g][idx];
    out[idx] = s;
}

extern "C" void kernel_launch(void* const* d_in, const int* in_sizes, int n_in,
                              void* d_out, int out_size) {
    (void)in_sizes; (void)n_in; (void)out_size;
    const float* W      = (const float*)d_in[0];
    const float* signs  = (const float*)d_in[1];
    const float* Xd     = (const float*)d_in[2];
    const float* Wshort = (const float*)d_in[3];
    const float* dmap   = (const float*)d_in[4];
    float* out = (float*)d_out;

    dim3 grid(NCHUNK, NOT);                       // 128 x 4 = 512 blocks
    delta_synapse_main<<<grid, NTHREADS>>>(W, signs, Xd, Wshort, dmap);
    reduce_stage1<<<dim3(BB * OO / 256, 8), 256>>>();
    reduce_stage2<<<BB * OO / 256, 256>>>(out);
}

// round 5
// speedup vs baseline: 1.5835x; 1.4230x over previous
#include <cuda_runtime.h>

// Problem constants (fixed by the dataset)
#define DD 16
#define BB 8
#define EE 2048
#define OO 2048

#define ECH    8                 // e's per chunk
#define NCHUNK (EE / ECH)        // 256
#define NTHREADS 128
#define OTILE  (NTHREADS * 4)    // 512 o's per block
#define NOT    (OO / OTILE)      // 4
#define PF     8                 // prefetch pipeline depth

// Scratch: per-e-chunk partial output [chunk][b][o] (256*8*2048*4B = 16 MB)
__device__ float g_partial[NCHUNK][BB][OO];
// Stage-1 reduce intermediate: [16 chunk-groups][B*O] = 1 MB
__device__ float g_p2[16][BB * OO];

__global__ __launch_bounds__(NTHREADS)
void delta_synapse_main(const float* __restrict__ W,
                        const float* __restrict__ signs,
                        const float* __restrict__ Xd,
                        const float* __restrict__ Wshort,
                        const float* __restrict__ dmap) {
    __shared__ float    coef[DD * BB][ECH];       // 4 KB: Xd*(Wshort+1)
    __shared__ float4   weffs[ECH][NTHREADS];     // 8 KB: W*signs slice
    __shared__ unsigned short wl[ECH * DD];       // worklist: el | d<<3 | bmask<<7
    __shared__ int wl_n;

    const int chunk = blockIdx.x;                 // 0..255
    const int otile = blockIdx.y;                 // 0..3
    const int e0    = chunk * ECH;
    const int obase = otile * OTILE + threadIdx.x * 4;

    if (threadIdx.x == 0) wl_n = 0;
    __syncthreads();

    // ---- Phase 1: coef[d*8+b][el] = Xd * (Wshort + 1)  (1024 elems, 8/thread)
    #pragma unroll
    for (int r = 0; r < (DD * BB * ECH) / NTHREADS; r++) {
        const int idx = r * NTHREADS + threadIdx.x;
        const int el  = idx & (ECH - 1);
        const int g   = idx >> 3;                  // d*8 + b
        const int gi  = g * EE + e0 + el;
        const float x = Xd[gi];
        coef[g][el] = x * (Wshort[gi] + 1.0f);
    }
    __syncthreads();

    // ---- Phase 2: one thread per (el,d) pair (8*16 = 128) builds bmask,
    //      compacts nonempty pairs into wl via smem atomic (order irrelevant)
    {
        const int el = threadIdx.x & (ECH - 1);
        const int d  = threadIdx.x >> 3;           // 0..15
        unsigned bm = 0;
        #pragma unroll
        for (int b = 0; b < BB; b++)
            if (coef[d * BB + b][el] != 0.0f) bm |= 1u << b;
        if (bm) {
            const int pos = atomicAdd(&wl_n, 1);
            wl[pos] = (unsigned short)(el | (d << 3) | (bm << 7));
        }
    }

    // ---- Phase 3: Weff = W*signs into smem (independent loads → full MLP)
    #pragma unroll
    for (int el = 0; el < ECH; el++) {
        const size_t row = (size_t)(e0 + el) * OO + obase;
        const float4 wv = __ldcs((const float4*)&W[row]);
        const float4 sv = __ldcs((const float4*)&signs[row]);
        weffs[el][threadIdx.x] =
            make_float4(wv.x * sv.x, wv.y * sv.y, wv.z * sv.z, wv.w * sv.w);
    }
    __syncthreads();

    float acc[BB][4];
    #pragma unroll
    for (int b = 0; b < BB; b++)
        #pragma unroll
        for (int j = 0; j < 4; j++) acc[b][j] = 0.0f;

    // ---- Phase 4: pipelined sweep; delaymap row is the only DRAM op
    const int n = wl_n;
    float4 buf[PF];
    #pragma unroll
    for (int j = 0; j < PF; j++) {
        if (j < n) {
            const int w = wl[j];
            const size_t a =
                ((size_t)((w >> 3) & 15) * EE + e0 + (w & 7)) * OO + obase;
            buf[j] = __ldcs((const float4*)&dmap[a]);
        }
    }

    for (int i = 0; i < n; i += PF) {
        #pragma unroll
        for (int j = 0; j < PF; j++) {
            const int k = i + j;
            if (k >= n) break;
            const int w  = wl[k];
            const int el = w & 7;
            const int d  = (w >> 3) & 15;
            unsigned bm  = w >> 7;
            const float4 dm = buf[j];

            const int p = k + PF;                  // keep PF loads in flight
            if (p < n) {
                const int w2 = wl[p];
                const size_t a =
                    ((size_t)((w2 >> 3) & 15) * EE + e0 + (w2 & 7)) * OO + obase;
                buf[j] = __ldcs((const float4*)&dmap[a]);
            }

            const float4 wv = weffs[el][threadIdx.x];
            const float t0 = wv.x * dm.x;
            const float t1 = wv.y * dm.y;
            const float t2 = wv.z * dm.z;
            const float t3 = wv.w * dm.w;
            while (bm) {                           // avg ~1.2 active batches
                const int b = __ffs(bm) - 1;
                bm &= bm - 1;
                const float c = coef[d * BB + b][el];   // smem broadcast
                acc[b][0] += t0 * c;
                acc[b][1] += t1 * c;
                acc[b][2] += t2 * c;
                acc[b][3] += t3 * c;
            }
        }
    }

    // ---- Phase 5: write partials (unconditional — scratch never zeroed)
    #pragma unroll
    for (int b = 0; b < BB; b++) {
        *(float4*)&g_partial[chunk][b][obase] =
            make_float4(acc[b][0], acc[b][1], acc[b][2], acc[b][3]);
    }
}

// Stage 1: (64 x 16) blocks — each sums 16 chunk-slices for 256 (b,o) positions
__global__ __launch_bounds__(256)
void reduce_stage1() {
    const int idx = blockIdx.x * 256 + threadIdx.x;   // 0 .. B*O-1
    const int g   = blockIdx.y;                       // chunk group 0..15
    const float* p = &g_partial[0][0][0];
    float s0 = 0.f, s1 = 0.f, s2 = 0.f, s3 = 0.f;
    const int c0 = g * 16;
    #pragma unroll
    for (int c = 0; c < 16; c += 4) {
        s0 += p[(size_t)(c0 + c + 0) * (BB * OO) + idx];
        s1 += p[(size_t)(c0 + c + 1) * (BB * OO) + idx];
        s2 += p[(size_t)(c0 + c + 2) * (BB * OO) + idx];
        s3 += p[(size_t)(c0 + c + 3) * (BB * OO) + idx];
    }
    g_p2[g][idx] = (s0 + s1) + (s2 + s3);
}

// Stage 2: sum the 16 group-partials into the output
__global__ __launch_bounds__(256)
void reduce_stage2(float* __restrict__ out) {
    const int idx = blockIdx.x * 256 + threadIdx.x;
    float s = 0.f;
    #pragma unroll
    for (int g = 0; g < 16; g++) s += g_p2[g][idx];
    out[idx] = s;
}

extern "C" void kernel_launch(void* const* d_in, const int* in_sizes, int n_in,
                              void* d_out, int out_size) {
    (void)in_sizes; (void)n_in; (void)out_size;
    const float* W      = (const float*)d_in[0];
    const float* signs  = (const float*)d_in[1];
    const float* Xd     = (const float*)d_in[2];
    const float* Wshort = (const float*)d_in[3];
    const float* dmap   = (const float*)d_in[4];
    float* out = (float*)d_out;

    dim3 grid(NCHUNK, NOT);                       // 256 x 4 = 1024 blocks
    delta_synapse_main<<<grid, NTHREADS>>>(W, signs, Xd, Wshort, dmap);
    reduce_stage1<<<dim3(BB * OO / 256, 16), 256>>>();
    reduce_stage2<<<BB * OO / 256, 256>>>(out);
}

// round 6
// speedup vs baseline: 1.7966x; 1.1346x over previous
#include <cuda_runtime.h>
#include <cstdint>

// Problem constants (fixed by the dataset)
#define DD 16
#define BB 8
#define EE 2048
#define OO 2048

#define ECH    8                 // e's per chunk
#define NCHUNK (EE / ECH)        // 256
#define NTHREADS 128
#define OTILE  (NTHREADS * 4)    // 512 o's per block
#define NOT    (OO / OTILE)      // 4
#define PF     4                 // prefetch pipeline depth

// Scratch: per-e-chunk partial output [chunk][b][o] (256*8*2048*4B = 16 MB)
__device__ float g_partial[NCHUNK][BB][OO];
// Stage-1 reduce intermediate: [16 chunk-groups][B*O] = 1 MB
__device__ float g_p2[16][BB * OO];

__global__ __launch_bounds__(NTHREADS, 6)
void delta_synapse_main(const float* __restrict__ W,
                        const float* __restrict__ signs,
                        const float* __restrict__ Xd,
                        const float* __restrict__ Wshort,
                        const float* __restrict__ dmap) {
    __shared__ float    coef[DD * BB][ECH];        // 4 KB: Xd*(Wshort+1)
    __shared__ float4   weffs[ECH][NTHREADS];      // 8 KB: W*signs slice
    // Packed worklist: low32 = element offset (d*EE+e)*OO, high32 = el|d<<3|bm<<7
    __shared__ uint64_t wl64[ECH * DD + 2 * PF];
    __shared__ int wl_n;
    __shared__ int wl_npad;

    const int chunk = blockIdx.x;                  // 0..255
    const int otile = blockIdx.y;                  // 0..3
    const int e0    = chunk * ECH;
    const int obase = otile * OTILE + threadIdx.x * 4;

    if (threadIdx.x == 0) wl_n = 0;
    __syncthreads();

    // ---- Phase 1: coef[d*8+b][el] = Xd * (Wshort + 1)  (1024 elems, 8/thread)
    #pragma unroll
    for (int r = 0; r < (DD * BB * ECH) / NTHREADS; r++) {
        const int idx = r * NTHREADS + threadIdx.x;
        const int el  = idx & (ECH - 1);
        const int g   = idx >> 3;                   // d*8 + b
        const int gi  = g * EE + e0 + el;
        const float x = Xd[gi];
        coef[g][el] = x * (Wshort[gi] + 1.0f);
    }
    __syncthreads();

    // ---- Phase 2: one thread per (el,d) pair (8*16 = 128): bmask + packed entry
    {
        const int el = threadIdx.x & (ECH - 1);
        const int d  = threadIdx.x >> 3;            // 0..15
        unsigned bm = 0;
        #pragma unroll
        for (int b = 0; b < BB; b++)
            if (coef[d * BB + b][el] != 0.0f) bm |= 1u << b;
        if (bm) {
            const int pos = atomicAdd(&wl_n, 1);
            const uint32_t off  = (uint32_t)(d * EE + e0 + el) * OO;
            const uint32_t meta = (uint32_t)(el | (d << 3) | (bm << 7));
            wl64[pos] = (uint64_t)off | ((uint64_t)meta << 32);
        }
    }

    // ---- Phase 3: Weff = W*signs into smem (independent loads → full MLP)
    #pragma unroll
    for (int el = 0; el < ECH; el++) {
        const size_t row = (size_t)(e0 + el) * OO + obase;
        const float4 wv = __ldcs((const float4*)&W[row]);
        const float4 sv = __ldcs((const float4*)&signs[row]);
        weffs[el][threadIdx.x] =
            make_float4(wv.x * sv.x, wv.y * sv.y, wv.z * sv.z, wv.w * sv.w);
    }
    __syncthreads();                                // wl_n final, weffs visible

    // ---- Pad worklist to PF multiple + PF sentinel entries (bm=0 → no-ops)
    if (threadIdx.x == 0) {
        const int n    = wl_n;
        const int npad = (n + PF - 1) & ~(PF - 1);
        for (int k = n; k < npad + PF; k++) wl64[k] = 0ull;
        wl_npad = npad;
    }
    __syncthreads();

    float4 acc[BB];
    #pragma unroll
    for (int b = 0; b < BB; b++) acc[b] = make_float4(0.f, 0.f, 0.f, 0.f);

    // ---- Phase 4: pipelined sweep; delaymap row is the only DRAM op
    const float* dbase = dmap + obase;
    const int npad = wl_npad;
    float4   buf[PF];
    uint32_t mbuf[PF];
    #pragma unroll
    for (int j = 0; j < PF; j++) {
        const uint64_t w = wl64[j];
        buf[j]  = __ldcs((const float4*)(dbase + (uint32_t)w));
        mbuf[j] = (uint32_t)(w >> 32);
    }

    for (int i = 0; i < npad; i += PF) {
        #pragma unroll
        for (int j = 0; j < PF; j++) {
            const float4   dm   = buf[j];
            const uint32_t meta = mbuf[j];

            const uint64_t w = wl64[i + j + PF];    // always in-bounds (padded)
            buf[j]  = __ldcs((const float4*)(dbase + (uint32_t)w));
            mbuf[j] = (uint32_t)(w >> 32);

            unsigned bm = meta >> 7;
            if (bm) {                               // warp-uniform
                const int el = meta & 7;
                const int d  = (meta >> 3) & 15;
                const float4 wv = weffs[el][threadIdx.x];
                const float t0 = wv.x * dm.x;
                const float t1 = wv.y * dm.y;
                const float t2 = wv.z * dm.z;
                const float t3 = wv.w * dm.w;
                const float* crow = &coef[d * BB][el];  // +b*ECH per batch
                while (bm) {                        // avg ~1.2 active batches
                    const int b = __ffs(bm) - 1;
                    bm &= bm - 1;
                    const float c = crow[b * ECH];  // smem broadcast
                    switch (b) {                    // static acc indexing
                    case 0: acc[0].x += t0*c; acc[0].y += t1*c; acc[0].z += t2*c; acc[0].w += t3*c; break;
                    case 1: acc[1].x += t0*c; acc[1].y += t1*c; acc[1].z += t2*c; acc[1].w += t3*c; break;
                    case 2: acc[2].x += t0*c; acc[2].y += t1*c; acc[2].z += t2*c; acc[2].w += t3*c; break;
                    case 3: acc[3].x += t0*c; acc[3].y += t1*c; acc[3].z += t2*c; acc[3].w += t3*c; break;
                    case 4: acc[4].x += t0*c; acc[4].y += t1*c; acc[4].z += t2*c; acc[4].w += t3*c; break;
                    case 5: acc[5].x += t0*c; acc[5].y += t1*c; acc[5].z += t2*c; acc[5].w += t3*c; break;
                    case 6: acc[6].x += t0*c; acc[6].y += t1*c; acc[6].z += t2*c; acc[6].w += t3*c; break;
                    default: acc[7].x += t0*c; acc[7].y += t1*c; acc[7].z += t2*c; acc[7].w += t3*c; break;
                    }
                }
            }
        }
    }

    // ---- Phase 5: write partials (unconditional — scratch never zeroed)
    #pragma unroll
    for (int b = 0; b < BB; b++)
        *(float4*)&g_partial[chunk][b][obase] = acc[b];
}

// Stage 1: (64 x 16) blocks — each sums 16 chunk-slices for 256 (b,o) positions
__global__ __launch_bounds__(256)
void reduce_stage1() {
    const int idx = blockIdx.x * 256 + threadIdx.x;   // 0 .. B*O-1
    const int g   = blockIdx.y;                       // chunk group 0..15
    const float* p = &g_partial[0][0][0];
    float s0 = 0.f, s1 = 0.f, s2 = 0.f, s3 = 0.f;
    const int c0 = g * 16;
    #pragma unroll
    for (int c = 0; c < 16; c += 4) {
        s0 += p[(size_t)(c0 + c + 0) * (BB * OO) + idx];
        s1 += p[(size_t)(c0 + c + 1) * (BB * OO) + idx];
        s2 += p[(size_t)(c0 + c + 2) * (BB * OO) + idx];
        s3 += p[(size_t)(c0 + c + 3) * (BB * OO) + idx];
    }
    g_p2[g][idx] = (s0 + s1) + (s2 + s3);
}

// Stage 2: sum the 16 group-partials into the output
__global__ __launch_bounds__(256)
void reduce_stage2(float* __restrict__ out) {
    const int idx = blockIdx.x * 256 + threadIdx.x;
    float s = 0.f;
    #pragma unroll
    for (int g = 0; g < 16; g++) s += g_p2[g][idx];
    out[idx] = s;
}

extern "C" void kernel_launch(void* const* d_in, const int* in_sizes, int n_in,
                              void* d_out, int out_size) {
    (void)in_sizes; (void)n_in; (void)out_size;
    const float* W      = (const float*)d_in[0];
    const float* signs  = (const float*)d_in[1];
    const float* Xd     = (const float*)d_in[2];
    const float* Wshort = (const float*)d_in[3];
    const float* dmap   = (const float*)d_in[4];
    float* out = (float*)d_out;

    dim3 grid(NCHUNK, NOT);                       // 256 x 4 = 1024 blocks
    delta_synapse_main<<<grid, NTHREADS>>>(W, signs, Xd, Wshort, dmap);
    reduce_stage1<<<dim3(BB * OO / 256, 16), 256>>>();
    reduce_stage2<<<BB * OO / 256, 256>>>(out);
}

// round 7
// speedup vs baseline: 2.6696x; 1.4859x over previous
#include <cuda_runtime.h>
#include <cstdint>

// Problem constants (fixed by the dataset)
#define DD 16
#define BB 8
#define EE 2048
#define OO 2048

#define ECH    8                 // e's per chunk
#define NCHUNK (EE / ECH)        // 256
#define NTHREADS 128
#define OTILE  (NTHREADS * 4)    // 512 o's per block
#define NOT    (OO / OTILE)      // 4
#define PF     3                 // prefetch pipeline depth

__global__ __launch_bounds__(256)
void zero_out(float* __restrict__ out) {
    out[blockIdx.x * 256 + threadIdx.x] = 0.0f;
}

__global__ __launch_bounds__(NTHREADS, 7)   // 148*7 = 1036 >= 1024 -> single wave
void delta_synapse_main(const float* __restrict__ W,
                        const float* __restrict__ signs,
                        const float* __restrict__ Xd,
                        const float* __restrict__ Wshort,
                        const float* __restrict__ dmap,
                        float* __restrict__ out) {
    __shared__ float    coef[DD * BB][ECH];        // 4 KB: Xd*(Wshort+1)
    __shared__ float4   weffs[ECH][NTHREADS];      // 8 KB: W*signs slice
    // Packed worklist: low32 = element offset (d*EE+e)*OO, high32 = el|d<<3|bm<<7
    __shared__ uint64_t wl64[ECH * DD + 2 * PF];
    __shared__ int wl_n;
    __shared__ int wl_npad;

    const int chunk = blockIdx.x;                  // 0..255
    const int otile = blockIdx.y;                  // 0..3
    const int e0    = chunk * ECH;
    const int obase = otile * OTILE + threadIdx.x * 4;

    if (threadIdx.x == 0) wl_n = 0;
    __syncthreads();

    // ---- Phase 1: coef[d*8+b][el] = Xd * (Wshort + 1)  (1024 elems, 8/thread)
    #pragma unroll
    for (int r = 0; r < (DD * BB * ECH) / NTHREADS; r++) {
        const int idx = r * NTHREADS + threadIdx.x;
        const int el  = idx & (ECH - 1);
        const int g   = idx >> 3;                   // d*8 + b
        const int gi  = g * EE + e0 + el;
        const float x = Xd[gi];
        coef[g][el] = x * (Wshort[gi] + 1.0f);
    }
    __syncthreads();

    // ---- Phase 2: one thread per (el,d) pair (8*16 = 128): bmask + packed entry
    {
        const int el = threadIdx.x & (ECH - 1);
        const int d  = threadIdx.x >> 3;            // 0..15
        unsigned bm = 0;
        #pragma unroll
        for (int b = 0; b < BB; b++)
            if (coef[d * BB + b][el] != 0.0f) bm |= 1u << b;
        if (bm) {
            const int pos = atomicAdd(&wl_n, 1);
            const uint32_t off  = (uint32_t)(d * EE + e0 + el) * OO;
            const uint32_t meta = (uint32_t)(el | (d << 3) | (bm << 7));
            wl64[pos] = (uint64_t)off | ((uint64_t)meta << 32);
        }
    }

    // ---- Phase 3: Weff = W*signs into smem (independent loads → full MLP)
    #pragma unroll
    for (int el = 0; el < ECH; el++) {
        const size_t row = (size_t)(e0 + el) * OO + obase;
        const float4 wv = __ldcs((const float4*)&W[row]);
        const float4 sv = __ldcs((const float4*)&signs[row]);
        weffs[el][threadIdx.x] =
            make_float4(wv.x * sv.x, wv.y * sv.y, wv.z * sv.z, wv.w * sv.w);
    }
    __syncthreads();                                // wl_n final, weffs visible

    // ---- Pad worklist to PF multiple + PF sentinel entries (bm=0 → no-ops)
    if (threadIdx.x == 0) {
        const int n    = wl_n;
        const int npad = (n + PF - 1) & ~(PF - 1);
        for (int k = n; k < npad + PF; k++) wl64[k] = 0ull;
        wl_npad = npad;
    }
    __syncthreads();

    float4 acc[BB];
    #pragma unroll
    for (int b = 0; b < BB; b++) acc[b] = make_float4(0.f, 0.f, 0.f, 0.f);

    // ---- Phase 4: pipelined sweep; delaymap row is the only DRAM op
    const float* dbase = dmap + obase;
    const int npad = wl_npad;
    float4   buf[PF];
    uint32_t mbuf[PF];
    #pragma unroll
    for (int j = 0; j < PF; j++) {
        const uint64_t w = wl64[j];
        buf[j]  = __ldcs((const float4*)(dbase + (uint32_t)w));
        mbuf[j] = (uint32_t)(w >> 32);
    }

    for (int i = 0; i < npad; i += PF) {
        #pragma unroll
        for (int j = 0; j < PF; j++) {
            const float4   dm   = buf[j];
            const uint32_t meta = mbuf[j];

            const uint64_t w = wl64[i + j + PF];    // always in-bounds (padded)
            buf[j]  = __ldcs((const float4*)(dbase + (uint32_t)w));
            mbuf[j] = (uint32_t)(w >> 32);

            unsigned bm = meta >> 7;
            if (bm) {                               // warp-uniform
                const int el = meta & 7;
                const int d  = (meta >> 3) & 15;
                const float4 wv = weffs[el][threadIdx.x];
                const float t0 = wv.x * dm.x;
                const float t1 = wv.y * dm.y;
                const float t2 = wv.z * dm.z;
                const float t3 = wv.w * dm.w;
                const float* crow = &coef[d * BB][el];  // +b*ECH per batch
                while (bm) {                        // avg ~1.2 active batches
                    const int b = __ffs(bm) - 1;
                    bm &= bm - 1;
                    const float c = crow[b * ECH];  // smem broadcast
                    switch (b) {                    // static acc indexing
                    case 0: acc[0].x += t0*c; acc[0].y += t1*c; acc[0].z += t2*c; acc[0].w += t3*c; break;
                    case 1: acc[1].x += t0*c; acc[1].y += t1*c; acc[1].z += t2*c; acc[1].w += t3*c; break;
                    case 2: acc[2].x += t0*c; acc[2].y += t1*c; acc[2].z += t2*c; acc[2].w += t3*c; break;
                    case 3: acc[3].x += t0*c; acc[3].y += t1*c; acc[3].z += t2*c; acc[3].w += t3*c; break;
                    case 4: acc[4].x += t0*c; acc[4].y += t1*c; acc[4].z += t2*c; acc[4].w += t3*c; break;
                    case 5: acc[5].x += t0*c; acc[5].y += t1*c; acc[5].z += t2*c; acc[5].w += t3*c; break;
                    case 6: acc[6].x += t0*c; acc[6].y += t1*c; acc[6].z += t2*c; acc[6].w += t3*c; break;
                    default: acc[7].x += t0*c; acc[7].y += t1*c; acc[7].z += t2*c; acc[7].w += t3*c; break;
                    }
                }
            }
        }
    }

    // ---- Phase 5: reduce directly into out via vector REDG (no return value).
    //      Per address only NCHUNK=256 adds over the whole kernel -> no contention.
    #pragma unroll
    for (int b = 0; b < BB; b++) {
        float* dst = out + b * OO + obase;
        asm volatile("red.global.add.v4.f32 [%0], {%1, %2, %3, %4};"
                     :: "l"(dst),
                        "f"(acc[b].x), "f"(acc[b].y), "f"(acc[b].z), "f"(acc[b].w)
                     : "memory");
    }
}

extern "C" void kernel_launch(void* const* d_in, const int* in_sizes, int n_in,
                              void* d_out, int out_size) {
    (void)in_sizes; (void)n_in; (void)out_size;
    const float* W      = (const float*)d_in[0];
    const float* signs  = (const float*)d_in[1];
    const float* Xd     = (const float*)d_in[2];
    const float* Wshort = (const float*)d_in[3];
    const float* dmap   = (const float*)d_in[4];
    float* out = (float*)d_out;

    zero_out<<<(BB * OO) / 256, 256>>>(out);
    dim3 grid(NCHUNK, NOT);                       // 256 x 4 = 1024 blocks, 1 wave
    delta_synapse_main<<<grid, NTHREADS>>>(W, signs, Xd, Wshort, dmap, out);
}